// round 2
// baseline (speedup 1.0000x reference)
#include <cuda_runtime.h>
#include <cuda_bf16.h>
#include <math.h>

#define NN 4096
#define IN_DIM 1433
#define HID 64
#define OUT_DIM 7
#define MAXDEG 160
#define SCAD_A 3.7f
#define LAMW ((float)(1.0/0.9 - 1.0))
#define K_STEPS 10

// ---------------- scratch (device globals; no allocation allowed) ----------------
__device__ float g_H[NN * HID];          // hidden activations
__device__ float g_F0[NN * 8];           // F0 padded stride 8
__device__ float g_Fa[NN * 8];           // F ping
__device__ float g_Fb[NN * 8];           // F pong
__device__ float g_FnA[NN * 8];          // normalized features ping
__device__ float g_FnB[NN * 8];          // normalized features pong
__device__ float g_sqA[NN];              // ||Fn||^2 ping
__device__ float g_sqB[NN];              // ||Fn||^2 pong
__device__ float g_rD[NN];               // 1/sqrt(D)
__device__ float g_D[NN];                // D
__device__ int   g_cols[NN * MAXDEG];    // ELL adjacency
__device__ int   g_deg[NN];

// ---------------- 1. build ELL adjacency + degrees (one pass over A) ----------------
__global__ void build_adj_kernel(const float* __restrict__ A) {
    int warp = (blockIdx.x * blockDim.x + threadIdx.x) >> 5;
    int lane = threadIdx.x & 31;
    if (warp >= NN) return;
    const float* row = A + (size_t)warp * NN;
    int* cols = g_cols + (size_t)warp * MAXDEG;
    int cnt = 0;
    for (int c = lane; c < NN; c += 32) {
        float v = row[c];
        bool nz = (v != 0.0f);
        unsigned m = __ballot_sync(0xffffffffu, nz);
        if (nz) {
            int pos = cnt + __popc(m & ((1u << lane) - 1u));
            if (pos < MAXDEG) cols[pos] = c;
        }
        cnt += __popc(m);
    }
    if (lane == 0) {
        int d = cnt < MAXDEG ? cnt : MAXDEG;
        g_deg[warp] = d;
        float D = (float)cnt + 1.0f;   // self loop
        g_D[warp] = D;
        g_rD[warp] = 1.0f / sqrtf(D);
    }
}

// ---------------- 2. MLP layer 1: H = relu(X @ w1 + b1) ----------------
#define MT 64
#define KT 32
__global__ void mlp1_kernel(const float* __restrict__ X,
                            const float* __restrict__ w1,
                            const float* __restrict__ b1) {
    __shared__ float Xs[KT][MT];        // [k][m]
    __shared__ float Ws[KT][HID];       // [k][n]
    int m0 = blockIdx.x * MT;
    int tid = threadIdx.x;              // 256 threads
    int tr = (tid / 16) * 4;            // row base within tile
    int tc = (tid % 16) * 4;            // col base
    float acc[4][4];
    #pragma unroll
    for (int r = 0; r < 4; r++)
        #pragma unroll
        for (int c = 0; c < 4; c++) acc[r][c] = 0.0f;

    for (int kk = 0; kk < IN_DIM; kk += KT) {
        for (int idx = tid; idx < MT * KT; idx += 256) {
            int mm = idx / KT, k = idx % KT;
            int gk = kk + k;
            Xs[k][mm] = (gk < IN_DIM) ? X[(size_t)(m0 + mm) * IN_DIM + gk] : 0.0f;
        }
        for (int idx = tid; idx < KT * HID; idx += 256) {
            int k = idx / HID, n = idx % HID;
            int gk = kk + k;
            Ws[k][n] = (gk < IN_DIM) ? w1[(size_t)gk * HID + n] : 0.0f;
        }
        __syncthreads();
        #pragma unroll
        for (int k = 0; k < KT; k++) {
            float a[4], b[4];
            #pragma unroll
            for (int r = 0; r < 4; r++) a[r] = Xs[k][tr + r];
            #pragma unroll
            for (int c = 0; c < 4; c++) b[c] = Ws[k][tc + c];
            #pragma unroll
            for (int r = 0; r < 4; r++)
                #pragma unroll
                for (int c = 0; c < 4; c++) acc[r][c] = fmaf(a[r], b[c], acc[r][c]);
        }
        __syncthreads();
    }
    #pragma unroll
    for (int r = 0; r < 4; r++)
        #pragma unroll
        for (int c = 0; c < 4; c++) {
            float v = acc[r][c] + b1[tc + c];
            g_H[(size_t)(m0 + tr + r) * HID + tc + c] = fmaxf(v, 0.0f);
        }
}

// ---------------- 3. MLP layer 2: F0 = H @ w2 + b2; seeds Fn/sq ping buffer ----------------
__global__ void mlp2_kernel(const float* __restrict__ w2,
                            const float* __restrict__ b2) {
    __shared__ float sw[HID * OUT_DIM];
    __shared__ float sb[OUT_DIM];
    for (int idx = threadIdx.x; idx < HID * OUT_DIM; idx += blockDim.x)
        sw[idx] = w2[idx];
    if (threadIdx.x < OUT_DIM) sb[threadIdx.x] = b2[threadIdx.x];
    __syncthreads();
    int i = blockIdx.x * blockDim.x + threadIdx.x;
    if (i >= NN) return;
    float acc[OUT_DIM];
    #pragma unroll
    for (int o = 0; o < OUT_DIM; o++) acc[o] = sb[o];
    const float* h = g_H + (size_t)i * HID;
    #pragma unroll 8
    for (int k = 0; k < HID; k++) {
        float hv = h[k];
        #pragma unroll
        for (int o = 0; o < OUT_DIM; o++) acc[o] = fmaf(hv, sw[k * OUT_DIM + o], acc[o]);
    }
    float rd = g_rD[i];
    float ss = 0.0f;
    #pragma unroll
    for (int o = 0; o < OUT_DIM; o++) {
        g_F0[i * 8 + o] = acc[o];
        float fn = acc[o] * rd;
        g_FnA[i * 8 + o] = fn;
        ss = fmaf(fn, fn, ss);
    }
    g_F0[i * 8 + 7] = 0.0f;
    g_FnA[i * 8 + 7] = 0.0f;
    g_FnB[i * 8 + 7] = 0.0f;
    g_sqA[i] = ss;
}

// ---------------- 4. per-iteration sparse row update (warp per row) ----------------
// Reads Fin / Fn_in / sq_in; writes Fout and (for the next iteration) Fn_out / sq_out.
__global__ void row_kernel(const float* __restrict__ Fin,
                           float* __restrict__ Fout, int ostride,
                           const float* __restrict__ Fn_in,
                           const float* __restrict__ sq_in,
                           float* __restrict__ Fn_out,
                           float* __restrict__ sq_out,
                           const float* __restrict__ lg0p,
                           const float* __restrict__ rawp,
                           int kstep) {
    int warp = (blockIdx.x * blockDim.x + threadIdx.x) >> 5;
    int lane = threadIdx.x & 31;
    if (warp >= NN) return;
    int i = warp;

    // lam_k = exp(log_g0) * r^k / SCAD_A
    float g0 = expf(lg0p[0]);
    float r  = 1.0f / (1.0f + expf(-rawp[0]));
    float gk = g0;
    for (int t = 0; t < kstep; t++) gk *= r;
    float lam = gk / SCAD_A;
    float alam = SCAD_A * lam;

    float fni[7];
    const float4* fnv = (const float4*)(Fn_in + i * 8);
    float4 fi0 = fnv[0], fi1 = fnv[1];
    fni[0] = fi0.x; fni[1] = fi0.y; fni[2] = fi0.z; fni[3] = fi0.w;
    fni[4] = fi1.x; fni[5] = fi1.y; fni[6] = fi1.z;
    float sqi = sq_in[i];
    float rdi = g_rD[i];
    int deg = g_deg[i];
    const int* cols = g_cols + (size_t)i * MAXDEG;

    float s = 0.0f;
    float acc[7] = {0.f, 0.f, 0.f, 0.f, 0.f, 0.f, 0.f};

    for (int e = lane; e < deg; e += 32) {
        int j = cols[e];
        const float4* fj = (const float4*)(Fn_in + j * 8);
        float4 a0 = fj[0], a1 = fj[1];
        float dot = fni[0] * a0.x + fni[1] * a0.y + fni[2] * a0.z + fni[3] * a0.w
                  + fni[4] * a1.x + fni[5] * a1.y + fni[6] * a1.z;
        float Z = fmaxf(sqi + sq_in[j] - 2.0f * dot, 0.0f);
        float y = sqrtf(Z);
        float w;
        if (y <= lam)        w = 1.0f;
        else if (y <= alam)  w = (alam - y) / ((SCAD_A - 1.0f) * fmaxf(y, 1e-12f));
        else                 w = 0.0f;
        if (isnan(w)) w = 1.0f;
        s += w;
        float coef = w * rdi * g_rD[j];
        const float4* fv = (const float4*)(Fin + j * 8);
        float4 f0 = fv[0], f1 = fv[1];
        acc[0] = fmaf(coef, f0.x, acc[0]);
        acc[1] = fmaf(coef, f0.y, acc[1]);
        acc[2] = fmaf(coef, f0.z, acc[2]);
        acc[3] = fmaf(coef, f0.w, acc[3]);
        acc[4] = fmaf(coef, f1.x, acc[4]);
        acc[5] = fmaf(coef, f1.y, acc[5]);
        acc[6] = fmaf(coef, f1.z, acc[6]);
    }
    // warp reduction
    #pragma unroll
    for (int off = 16; off > 0; off >>= 1) {
        s += __shfl_down_sync(0xffffffffu, s, off);
        #pragma unroll
        for (int c = 0; c < 7; c++)
            acc[c] += __shfl_down_sync(0xffffffffu, acc[c], off);
    }
    if (lane == 0) {
        float Q = s / g_D[i] + LAMW;
        float invQ = 1.0f / Q;
        float ss = 0.0f;
        #pragma unroll
        for (int c = 0; c < 7; c++) {
            float f = (acc[c] + LAMW * g_F0[i * 8 + c]) * invQ;
            Fout[(size_t)i * ostride + c] = f;
            float fn = f * rdi;
            Fn_out[i * 8 + c] = fn;
            ss = fmaf(fn, fn, ss);
        }
        sq_out[i] = ss;
    }
}

// ---------------- launch ----------------
extern "C" void kernel_launch(void* const* d_in, const int* in_sizes, int n_in,
                              void* d_out, int out_size) {
    // Bind inputs by element count (robust to metadata ordering).
    const float *A = nullptr, *X = nullptr, *w1 = nullptr, *b1 = nullptr,
                *w2 = nullptr, *b2 = nullptr, *lg0 = nullptr, *raw = nullptr;
    for (int t = 0; t < n_in; t++) {
        int sz = in_sizes[t];
        const float* p = (const float*)d_in[t];
        if      (sz == NN * NN)        A  = p;
        else if (sz == NN * IN_DIM)    X  = p;
        else if (sz == IN_DIM * HID)   w1 = p;
        else if (sz == HID)            b1 = p;
        else if (sz == HID * OUT_DIM)  w2 = p;
        else if (sz == OUT_DIM)        b2 = p;
        else if (sz == 1) { if (!lg0) lg0 = p; else raw = p; }
    }
    float* out = (float*)d_out;

    build_adj_kernel<<<(NN * 32 + 255) / 256, 256>>>(A);
    mlp1_kernel<<<NN / MT, 256>>>(X, w1, b1);
    mlp2_kernel<<<(NN + 255) / 256, 256>>>(w2, b2);

    float *Fa, *Fb, *F0, *FnA, *FnB, *sqA, *sqB;
    cudaGetSymbolAddress((void**)&Fa, g_Fa);
    cudaGetSymbolAddress((void**)&Fb, g_Fb);
    cudaGetSymbolAddress((void**)&F0, g_F0);
    cudaGetSymbolAddress((void**)&FnA, g_FnA);
    cudaGetSymbolAddress((void**)&FnB, g_FnB);
    cudaGetSymbolAddress((void**)&sqA, g_sqA);
    cudaGetSymbolAddress((void**)&sqB, g_sqB);

    const float* Fin = F0;   // F starts at F0
    for (int k = 0; k < K_STEPS; k++) {
        bool last = (k == K_STEPS - 1);
        float* Fout = last ? out : ((k & 1) ? Fb : Fa);
        int ostride = last ? OUT_DIM : 8;
        const float* Fn_in = (k & 1) ? FnB : FnA;
        const float* sq_in = (k & 1) ? sqB : sqA;
        float* Fn_out = (k & 1) ? FnA : FnB;
        float* sq_out = (k & 1) ? sqA : sqB;
        row_kernel<<<(NN * 32 + 255) / 256, 256>>>(Fin, Fout, ostride,
                                                   Fn_in, sq_in, Fn_out, sq_out,
                                                   lg0, raw, k);
        Fin = Fout;
    }
}

// round 3
// speedup vs baseline: 1.6761x; 1.6761x over previous
#include <cuda_runtime.h>
#include <cuda_bf16.h>
#include <math.h>

#define NN 4096
#define IN_DIM 1433
#define HID 64
#define OUT_DIM 7
#define MAXDEG 160
#define SCAD_A 3.7f
#define LAMW ((float)(1.0/0.9 - 1.0))
#define K_STEPS 10
#define KT 32
#define NTILE ((IN_DIM + KT - 1) / KT)   // 45

// ---------------- scratch (device globals; no allocation allowed) ----------------
__device__ float g_H[NN * HID];          // hidden activations
__device__ float g_F0[NN * 8];           // F0 padded stride 8
__device__ float g_NdA[NN * 8];          // node pack ping: {Fn[0..6], sq}
__device__ float g_NdB[NN * 8];          // node pack pong
__device__ float g_rD[NN];               // 1/sqrt(D)
__device__ float g_D[NN];                // D
__device__ int   g_cols[NN * MAXDEG];    // ELL adjacency
__device__ int   g_deg[NN];

// ---- packed fp32x2 helpers ----
__device__ __forceinline__ unsigned long long pack_dup(float v) {
    unsigned long long r;
    asm("mov.b64 %0, {%1, %1};" : "=l"(r) : "f"(v));
    return r;
}
__device__ __forceinline__ void fma2(unsigned long long& d,
                                     unsigned long long a, unsigned long long b) {
    asm("fma.rn.f32x2 %0, %1, %2, %0;" : "+l"(d) : "l"(a), "l"(b));
}
__device__ __forceinline__ void unpack2(unsigned long long p, float& lo, float& hi) {
    asm("mov.b64 {%0, %1}, %2;" : "=f"(lo), "=f"(hi) : "l"(p));
}

// ---------------- 1. fused: build ELL adjacency  +  MLP layer 1 ----------------
// blocks [0,128):   adjacency, 32 rows per block (8 warps x 4 rows), float4 scan
// blocks [128,256): mlp1, 32 output rows per block, FFMA2 microkernel
__global__ __launch_bounds__(256, 2)
void fused_build_mlp1(const float* __restrict__ A,
                      const float* __restrict__ X,
                      const float* __restrict__ w1,
                      const float* __restrict__ b1) {
    __shared__ __align__(16) float Xs[KT][34];   // [k][m], padded stride 34
    __shared__ __align__(16) float Ws[KT][HID];  // [k][n]
    int tid = threadIdx.x;

    if (blockIdx.x < 128) {
        // ---------- adjacency part ----------
        int warp = tid >> 5;
        int lane = tid & 31;
        int rbase = blockIdx.x * 32 + warp * 4;
        for (int rr = 0; rr < 4; rr++) {
            int r = rbase + rr;
            const float4* row4 = (const float4*)(A + (size_t)r * NN);
            int* cols = g_cols + (size_t)r * MAXDEG;
            int cnt = 0;
            for (int c0 = 0; c0 < NN / 4; c0 += 32) {
                float4 v = row4[c0 + lane];
                int cb = (c0 + lane) * 4;
                #pragma unroll
                for (int e = 0; e < 4; e++) {
                    float f = (e == 0) ? v.x : (e == 1) ? v.y : (e == 2) ? v.z : v.w;
                    bool nz = (f != 0.0f);
                    unsigned m = __ballot_sync(0xffffffffu, nz);
                    if (nz) {
                        int pos = cnt + __popc(m & ((1u << lane) - 1u));
                        if (pos < MAXDEG) cols[pos] = cb + e;
                    }
                    cnt += __popc(m);
                }
            }
            if (lane == 0) {
                g_deg[r] = cnt < MAXDEG ? cnt : MAXDEG;
                float D = (float)cnt + 1.0f;   // self loop
                g_D[r] = D;
                g_rD[r] = 1.0f / sqrtf(D);
            }
        }
    } else {
        // ---------- mlp1 part: H = relu(X @ w1 + b1), MT=32 rows ----------
        int m0 = (blockIdx.x - 128) * 32;
        int tx = tid & 15;           // col group: cols tx*4..+3
        int ty = tid >> 4;           // row pair: rows ty*2, ty*2+1
        unsigned long long accp[4] = {0ull, 0ull, 0ull, 0ull};
        float xr[4], wr[8];

        // prefetch tile 0
        {
            #pragma unroll
            for (int j = 0; j < 4; j++) {
                int idx = tid + j * 256;
                int k = idx & 31, m = idx >> 5;
                xr[j] = (k < IN_DIM) ? X[(size_t)(m0 + m) * IN_DIM + k] : 0.0f;
            }
            #pragma unroll
            for (int j = 0; j < 8; j++) {
                int idx = tid + j * 256;
                int k = idx >> 6, n = idx & 63;
                wr[j] = (k < IN_DIM) ? w1[(size_t)k * HID + n] : 0.0f;
            }
        }

        for (int t = 0; t < NTILE; t++) {
            __syncthreads();
            #pragma unroll
            for (int j = 0; j < 4; j++) {
                int idx = tid + j * 256;
                Xs[idx & 31][idx >> 5] = xr[j];
            }
            #pragma unroll
            for (int j = 0; j < 8; j++) {
                int idx = tid + j * 256;
                Ws[idx >> 6][idx & 63] = wr[j];
            }
            __syncthreads();

            if (t + 1 < NTILE) {
                int kt = (t + 1) * KT;
                #pragma unroll
                for (int j = 0; j < 4; j++) {
                    int idx = tid + j * 256;
                    int k = kt + (idx & 31), m = idx >> 5;
                    xr[j] = (k < IN_DIM) ? X[(size_t)(m0 + m) * IN_DIM + k] : 0.0f;
                }
                #pragma unroll
                for (int j = 0; j < 8; j++) {
                    int idx = tid + j * 256;
                    int k = kt + (idx >> 6), n = idx & 63;
                    wr[j] = (k < IN_DIM) ? w1[(size_t)k * HID + n] : 0.0f;
                }
            }

            #pragma unroll
            for (int k = 0; k < KT; k++) {
                unsigned long long ap = *(const unsigned long long*)&Xs[k][ty * 2];
                float4 bv = *(const float4*)&Ws[k][tx * 4];
                fma2(accp[0], ap, pack_dup(bv.x));
                fma2(accp[1], ap, pack_dup(bv.y));
                fma2(accp[2], ap, pack_dup(bv.z));
                fma2(accp[3], ap, pack_dup(bv.w));
            }
        }

        float4 bb = *(const float4*)&b1[tx * 4];
        float blo[4] = {bb.x, bb.y, bb.z, bb.w};
        int r0 = m0 + ty * 2;
        #pragma unroll
        for (int c = 0; c < 4; c++) {
            float lo, hi;
            unpack2(accp[c], lo, hi);
            g_H[(size_t)r0 * HID + tx * 4 + c]       = fmaxf(lo + blo[c], 0.0f);
            g_H[(size_t)(r0 + 1) * HID + tx * 4 + c] = fmaxf(hi + blo[c], 0.0f);
        }
    }
}

// ---------------- 2. MLP layer 2: F0 = H @ w2 + b2; seeds node pack A ----------------
__global__ void mlp2_kernel(const float* __restrict__ w2,
                            const float* __restrict__ b2) {
    __shared__ float sw[HID * OUT_DIM];
    __shared__ float sb[OUT_DIM];
    for (int idx = threadIdx.x; idx < HID * OUT_DIM; idx += blockDim.x)
        sw[idx] = w2[idx];
    if (threadIdx.x < OUT_DIM) sb[threadIdx.x] = b2[threadIdx.x];
    __syncthreads();
    int i = blockIdx.x * blockDim.x + threadIdx.x;
    if (i >= NN) return;
    float acc[OUT_DIM];
    #pragma unroll
    for (int o = 0; o < OUT_DIM; o++) acc[o] = sb[o];
    const float* h = g_H + (size_t)i * HID;
    #pragma unroll 8
    for (int k = 0; k < HID; k++) {
        float hv = h[k];
        #pragma unroll
        for (int o = 0; o < OUT_DIM; o++) acc[o] = fmaf(hv, sw[k * OUT_DIM + o], acc[o]);
    }
    float rd = g_rD[i];
    float fn[7];
    float ss = 0.0f;
    #pragma unroll
    for (int o = 0; o < OUT_DIM; o++) {
        g_F0[i * 8 + o] = acc[o];
        fn[o] = acc[o] * rd;
        ss = fmaf(fn[o], fn[o], ss);
    }
    g_F0[i * 8 + 7] = 0.0f;
    float4* nd = (float4*)(g_NdA + i * 8);
    nd[0] = make_float4(fn[0], fn[1], fn[2], fn[3]);
    nd[1] = make_float4(fn[4], fn[5], fn[6], ss);
}

// ---------------- 3. per-iteration sparse row update (warp per row) ----------------
// acc[c] = sum_j w_ij * Fn_j[c];  F_i = (rD_i*acc + LAM*F0_i) / Q_i
__global__ void row_kernel(float* __restrict__ Fout, int ostride,
                           const float* __restrict__ Nd_in,
                           float* __restrict__ Nd_out,
                           const float* __restrict__ lg0p,
                           const float* __restrict__ rawp,
                           int kstep) {
    int warp = (blockIdx.x * blockDim.x + threadIdx.x) >> 5;
    int lane = threadIdx.x & 31;
    if (warp >= NN) return;
    int i = warp;

    float g0 = expf(lg0p[0]);
    float r  = 1.0f / (1.0f + expf(-rawp[0]));
    float gk = g0;
    for (int t = 0; t < kstep; t++) gk *= r;
    float lam = gk / SCAD_A;
    float alam = SCAD_A * lam;

    const float4* ndv = (const float4*)(Nd_in + i * 8);
    float4 fi0 = __ldg(ndv), fi1 = __ldg(ndv + 1);
    float fni[7] = {fi0.x, fi0.y, fi0.z, fi0.w, fi1.x, fi1.y, fi1.z};
    float sqi = fi1.w;
    float rdi = g_rD[i];
    int deg = g_deg[i];
    const int* cols = g_cols + (size_t)i * MAXDEG;

    float s = 0.0f;
    float acc[7] = {0.f, 0.f, 0.f, 0.f, 0.f, 0.f, 0.f};

    for (int e = lane; e < deg; e += 32) {
        int j = cols[e];
        const float4* nj = (const float4*)(Nd_in + j * 8);
        float4 a0 = __ldg(nj), a1 = __ldg(nj + 1);
        float dot = fni[0] * a0.x + fni[1] * a0.y + fni[2] * a0.z + fni[3] * a0.w
                  + fni[4] * a1.x + fni[5] * a1.y + fni[6] * a1.z;
        float Z = fmaxf(sqi + a1.w - 2.0f * dot, 0.0f);
        float y = sqrtf(Z);
        float w;
        if (y <= lam)        w = 1.0f;
        else if (y <= alam)  w = (alam - y) / ((SCAD_A - 1.0f) * fmaxf(y, 1e-12f));
        else                 w = 0.0f;
        s += w;
        acc[0] = fmaf(w, a0.x, acc[0]);
        acc[1] = fmaf(w, a0.y, acc[1]);
        acc[2] = fmaf(w, a0.z, acc[2]);
        acc[3] = fmaf(w, a0.w, acc[3]);
        acc[4] = fmaf(w, a1.x, acc[4]);
        acc[5] = fmaf(w, a1.y, acc[5]);
        acc[6] = fmaf(w, a1.z, acc[6]);
    }
    #pragma unroll
    for (int off = 16; off > 0; off >>= 1) {
        s += __shfl_down_sync(0xffffffffu, s, off);
        #pragma unroll
        for (int c = 0; c < 7; c++)
            acc[c] += __shfl_down_sync(0xffffffffu, acc[c], off);
    }
    if (lane == 0) {
        float Q = s / g_D[i] + LAMW;
        float invQ = 1.0f / Q;
        float fn[7];
        float ss = 0.0f;
        #pragma unroll
        for (int c = 0; c < 7; c++) {
            float f = (rdi * acc[c] + LAMW * g_F0[i * 8 + c]) * invQ;
            Fout[(size_t)i * ostride + c] = f;
            fn[c] = f * rdi;
            ss = fmaf(fn[c], fn[c], ss);
        }
        float4* nd = (float4*)(Nd_out + i * 8);
        nd[0] = make_float4(fn[0], fn[1], fn[2], fn[3]);
        nd[1] = make_float4(fn[4], fn[5], fn[6], ss);
    }
}

// dummy F output buffers for intermediate iterations (only last writes d_out)
__device__ float g_Ftmp[NN * 8];

// ---------------- launch ----------------
extern "C" void kernel_launch(void* const* d_in, const int* in_sizes, int n_in,
                              void* d_out, int out_size) {
    const float *A = nullptr, *X = nullptr, *w1 = nullptr, *b1 = nullptr,
                *w2 = nullptr, *b2 = nullptr, *lg0 = nullptr, *raw = nullptr;
    for (int t = 0; t < n_in; t++) {
        int sz = in_sizes[t];
        const float* p = (const float*)d_in[t];
        if      (sz == NN * NN)        A  = p;
        else if (sz == NN * IN_DIM)    X  = p;
        else if (sz == IN_DIM * HID)   w1 = p;
        else if (sz == HID)            b1 = p;
        else if (sz == HID * OUT_DIM)  w2 = p;
        else if (sz == OUT_DIM)        b2 = p;
        else if (sz == 1) { if (!lg0) lg0 = p; else raw = p; }
    }
    float* out = (float*)d_out;

    fused_build_mlp1<<<256, 256>>>(A, X, w1, b1);
    mlp2_kernel<<<(NN + 255) / 256, 256>>>(w2, b2);

    float *NdA, *NdB, *Ftmp;
    cudaGetSymbolAddress((void**)&NdA, g_NdA);
    cudaGetSymbolAddress((void**)&NdB, g_NdB);
    cudaGetSymbolAddress((void**)&Ftmp, g_Ftmp);

    for (int k = 0; k < K_STEPS; k++) {
        bool last = (k == K_STEPS - 1);
        float* Fout = last ? out : Ftmp;
        int ostride = last ? OUT_DIM : 8;
        const float* Nd_in = (k & 1) ? NdB : NdA;
        float* Nd_out = (k & 1) ? NdA : NdB;
        row_kernel<<<(NN * 32 + 255) / 256, 256>>>(Fout, ostride,
                                                   Nd_in, Nd_out, lg0, raw, k);
    }
}